// round 4
// baseline (speedup 1.0000x reference)
#include <cuda_runtime.h>
#include <cstdint>

// ============================================================================
// ConvLSTMEncoder: K=3 conv over a length-1 spatial dim == center tap only ->
// plain 3-layer LSTM. B=256, T=512, CIN=64, H=128.
//   gates[b, 4H] = [in; h] @ Wc^T + bias
// Round-3 structure:
//   - 128 CTAs = 16 clusters x 8 CTAs. Cluster == batch-group (16 batches);
//     CTA rank == gate-slice (16 hidden units x 4 gates = 64 rows/layer).
//   - Weights (fp32, center tap) resident in SMEM (180 KB/CTA).
//   - h state lives in the PRODUCER's smem (double-buffered); consumers pull
//     via ld.shared::cluster (DSMEM). Sync = barrier.cluster (no global mem).
//   - 256 threads (2 warps/SMSP) GEMV with k-split + fma.rn.f32x2, z stored
//     as duplicated (z,z) u64 pairs, row stride 18 (even -> LDS.128 for z).
//   - c state and biases in registers (thread (u,b) is fixed across t).
// ============================================================================

#define T_STEPS 512
#define CINX    64

// smem layout (bytes):
#define OFF_ZD    180224                 // u64 [256][18]          (36864 B)
#define OFF_GB    217088                 // float [2][64][17]      ( 8704 B)
#define OFF_HOWN  225792                 // float [6][16][16]      ( 6144 B)
#define SMEM_TOTAL 231936

__device__ __forceinline__ unsigned long long pack2f(float v) {
    unsigned u = __float_as_uint(v);
    return ((unsigned long long)u << 32) | (unsigned long long)u;
}
__device__ __forceinline__ float lo32(unsigned long long p) { return __uint_as_float((unsigned)p); }
__device__ __forceinline__ float hi32(unsigned long long p) { return __uint_as_float((unsigned)(p >> 32)); }

__device__ __forceinline__ float fast_rcp(float x) {
    float r; asm("rcp.approx.f32 %0, %1;" : "=f"(r) : "f"(x)); return r;
}
__device__ __forceinline__ float sigm(float x) {
    return fast_rcp(1.0f + __expf(-x));
}
__device__ __forceinline__ float tanh_f(float x) {
    x = fminf(fmaxf(x, -15.0f), 15.0f);
    float e = __expf(-2.0f * x);
    return (1.0f - e) * fast_rcp(1.0f + e);
}

#define FMA2(acc, a, b) asm("fma.rn.f32x2 %0, %1, %2, %0;" : "+l"(acc) : "l"(a), "l"(b))

__device__ __forceinline__ void cluster_sync() {
    asm volatile("barrier.cluster.arrive.aligned;" ::: "memory");
    asm volatile("barrier.cluster.wait.aligned;" ::: "memory");
}

// Read 16B from peer CTA's smem (rank within cluster) via DSMEM.
__device__ __forceinline__ float4 dsm_ld4(uint32_t local_addr, uint32_t rank) {
    uint32_t ra; float4 v;
    asm volatile("mapa.shared::cluster.u32 %0, %1, %2;" : "=r"(ra) : "r"(local_addr), "r"(rank));
    asm volatile("ld.shared::cluster.v4.f32 {%0,%1,%2,%3}, [%4];"
                 : "=f"(v.x), "=f"(v.y), "=f"(v.z), "=f"(v.w) : "r"(ra));
    return v;
}

// One layer phase: assemble zd, GEMV (k-split), cell, publish h, cluster sync.
template<int L, int KD>
__device__ __forceinline__ void do_layer(
    unsigned char* smraw, uint32_t hown_addr,
    const float* __restrict__ x, float* __restrict__ out,
    int t, int pc, int pp, int tid, int gid, int bgb,
    float4 bL, float& cre)
{
    unsigned long long* zd   = (unsigned long long*)(smraw + OFF_ZD);
    float*              gbuf = (float*)(smraw + OFF_GB);
    float*              hown = (float*)(smraw + OFF_HOWN);

    // ---- assemble duplicated input vector zd[k][b] = (z,z), stride 18 ----
    if (L == 0) {
        const float* xb = x + (size_t)bgb * (T_STEPS * CINX) + (size_t)t * CINX;
        float xv[4];
#pragma unroll
        for (int i = 0; i < 4; i++) {
            int idx = tid + (i << 8);
            int bb = idx >> 6, k = idx & 63;
            xv[i] = __ldg(&xb[(size_t)bb * (T_STEPS * CINX) + k]);
        }
        float4 hv[2]; int Uv[2], c4v[2];
#pragma unroll
        for (int i = 0; i < 2; i++) {
            int idx = tid + (i << 8);
            int U = idx >> 2, c4 = (idx & 3) << 2;
            Uv[i] = U; c4v[i] = c4;
            hv[i] = dsm_ld4(hown_addr + (((0 * 2 + pp) << 8) + ((U & 15) << 4) + c4) * 4,
                            (uint32_t)(U >> 4));
        }
#pragma unroll
        for (int i = 0; i < 4; i++) {
            int idx = tid + (i << 8);
            int bb = idx >> 6, k = idx & 63;
            zd[k * 18 + bb] = pack2f(xv[i]);
        }
#pragma unroll
        for (int i = 0; i < 2; i++) {
            unsigned long long* d = &zd[(64 + Uv[i]) * 18 + c4v[i]];
            *(ulonglong2*)(d)     = make_ulonglong2(pack2f(hv[i].x), pack2f(hv[i].y));
            *(ulonglong2*)(d + 2) = make_ulonglong2(pack2f(hv[i].z), pack2f(hv[i].w));
        }
    } else {
        float4 hv[4]; int Uv[2], c4v[2];
#pragma unroll
        for (int i = 0; i < 2; i++) {
            int idx = tid + (i << 8);
            int U = idx >> 2, c4 = (idx & 3) << 2;
            Uv[i] = U; c4v[i] = c4;
            int off = ((U & 15) << 4) + c4;
            hv[i]     = dsm_ld4(hown_addr + ((((L - 1) * 2 + pc) << 8) + off) * 4,
                                (uint32_t)(U >> 4));   // h_{L-1}(t)
            hv[2 + i] = dsm_ld4(hown_addr + (((L * 2 + pp) << 8) + off) * 4,
                                (uint32_t)(U >> 4));   // h_L(t-1)
        }
#pragma unroll
        for (int i = 0; i < 2; i++) {
            unsigned long long* d0 = &zd[Uv[i] * 18 + c4v[i]];
            *(ulonglong2*)(d0)     = make_ulonglong2(pack2f(hv[i].x), pack2f(hv[i].y));
            *(ulonglong2*)(d0 + 2) = make_ulonglong2(pack2f(hv[i].z), pack2f(hv[i].w));
            unsigned long long* d1 = &zd[(128 + Uv[i]) * 18 + c4v[i]];
            *(ulonglong2*)(d1)     = make_ulonglong2(pack2f(hv[2 + i].x), pack2f(hv[2 + i].y));
            *(ulonglong2*)(d1 + 2) = make_ulonglong2(pack2f(hv[2 + i].z), pack2f(hv[2 + i].w));
        }
    }
    __syncthreads();

    // ---- GEMV slice, k-split over warp pairs ----
    const int warp = tid >> 5, lane = tid & 31;
    const int wk = warp & 1, warpb = (warp >> 1) & 1, warpq = warp >> 2;
    const int qq = lane & 7, pq = lane >> 3;
    const int quad = (warpq << 3) | qq;             // 0..15 (4 rows each)
    const int b0 = ((warpb << 2) | pq) << 1;        // even batch index
    const int layer_off = (L == 0) ? 0 : (L == 1) ? 12288 : 28672;
    const int kofs = wk * (KD / 2);

    const float* Wl = (const float*)smraw + layer_off + (quad << 2) + (kofs << 6);
    const unsigned long long* zb = zd + kofs * 18 + b0;
    unsigned long long a00 = 0, a01 = 0, a10 = 0, a11 = 0;
#pragma unroll 8
    for (int k = 0; k < KD / 2; k++) {
        ulonglong2 w = *(const ulonglong2*)(Wl + (k << 6));  // rows 4q..4q+3, col k
        ulonglong2 z = *(const ulonglong2*)(zb + k * 18);    // batches b0, b0+1 (dup)
        FMA2(a00, w.x, z.x); FMA2(a01, w.x, z.y);
        FMA2(a10, w.y, z.x); FMA2(a11, w.y, z.y);
    }
    float* gb = gbuf + wk * 1088;
    const int r0 = quad << 2;
    gb[(r0 + 0) * 17 + b0]     = lo32(a00);
    gb[(r0 + 1) * 17 + b0]     = hi32(a00);
    gb[(r0 + 0) * 17 + b0 + 1] = lo32(a01);
    gb[(r0 + 1) * 17 + b0 + 1] = hi32(a01);
    gb[(r0 + 2) * 17 + b0]     = lo32(a10);
    gb[(r0 + 3) * 17 + b0]     = hi32(a10);
    gb[(r0 + 2) * 17 + b0 + 1] = lo32(a11);
    gb[(r0 + 3) * 17 + b0 + 1] = hi32(a11);
    __syncthreads();

    // ---- LSTM cell: one (u,b) per thread, c and bias in registers ----
    const int u = tid >> 4, bb = tid & 15;
    float gi = gbuf[u * 17 + bb]        + gbuf[1088 + u * 17 + bb]        + bL.x;
    float gf = gbuf[(16 + u) * 17 + bb] + gbuf[1088 + (16 + u) * 17 + bb] + bL.y;
    float go = gbuf[(32 + u) * 17 + bb] + gbuf[1088 + (32 + u) * 17 + bb] + bL.z;
    float gg = gbuf[(48 + u) * 17 + bb] + gbuf[1088 + (48 + u) * 17 + bb] + bL.w;
    float cn = sigm(gf) * cre + sigm(gi) * tanh_f(gg);
    float hn = sigm(go) * tanh_f(cn);
    cre = cn;
    hown[((L * 2 + pc) << 8) + (u << 4) + bb] = hn;
    if (L == 2 && t == T_STEPS - 1)
        out[(size_t)(bgb + bb) * 128 + (gid << 4) + u] = hn;
    cluster_sync();
}

__global__ void __cluster_dims__(8, 1, 1) __launch_bounds__(256, 1)
convlstm_kernel(
    const float* __restrict__ x,
    const float* __restrict__ W1, const float* __restrict__ b1,
    const float* __restrict__ W2, const float* __restrict__ b2,
    const float* __restrict__ W3, const float* __restrict__ b3,
    const float* __restrict__ h1i, const float* __restrict__ c1i,
    const float* __restrict__ h2i, const float* __restrict__ c2i,
    const float* __restrict__ h3i, const float* __restrict__ c3i,
    float* __restrict__ out)
{
    extern __shared__ unsigned char smraw[];
    float* Wsm  = (float*)smraw;
    float* hown = (float*)(smraw + OFF_HOWN);
    const uint32_t hown_addr = (uint32_t)__cvta_generic_to_shared(smraw + OFF_HOWN);

    const int tid = threadIdx.x;
    const int gid = blockIdx.x & 7;    // cluster rank == gate slice
    const int bg  = blockIdx.x >> 3;   // batch group
    const int bgb = bg << 4;

    // ---- Prologue: weight slices (center tap), transposed to [k][row64] ----
    for (int idx = tid; idx < 192 * 64; idx += 256) {
        int k = idx >> 6, r = idx & 63;
        int grow = ((r >> 4) << 7) | (gid << 4) | (r & 15);
        Wsm[idx] = W1[(size_t)grow * 576 + k * 3 + 1];
    }
    for (int idx = tid; idx < 256 * 64; idx += 256) {
        int k = idx >> 6, r = idx & 63;
        int grow = ((r >> 4) << 7) | (gid << 4) | (r & 15);
        Wsm[12288 + idx] = W2[(size_t)grow * 768 + k * 3 + 1];
        Wsm[28672 + idx] = W3[(size_t)grow * 768 + k * 3 + 1];
    }

    // ---- per-thread (u,b) registers: bias + c state ----
    const int u = tid >> 4, b = tid & 15;
    const int gub = (gid << 4) | u;
    float4 bL0 = make_float4(__ldg(&b1[0 * 128 + gub]), __ldg(&b1[1 * 128 + gub]),
                             __ldg(&b1[2 * 128 + gub]), __ldg(&b1[3 * 128 + gub]));
    float4 bL1 = make_float4(__ldg(&b2[0 * 128 + gub]), __ldg(&b2[1 * 128 + gub]),
                             __ldg(&b2[2 * 128 + gub]), __ldg(&b2[3 * 128 + gub]));
    float4 bL2 = make_float4(__ldg(&b3[0 * 128 + gub]), __ldg(&b3[1 * 128 + gub]),
                             __ldg(&b3[2 * 128 + gub]), __ldg(&b3[3 * 128 + gub]));
    const int sidx = (bgb + b) * 128 + gub;
    float c1r = __ldg(&c1i[sidx]);
    float c2r = __ldg(&c2i[sidx]);
    float c3r = __ldg(&c3i[sidx]);

    // ---- initial h into local hown (parity 1 = "previous" at t=0) ----
    hown[((0 * 2 + 1) << 8) + (u << 4) + b] = __ldg(&h1i[sidx]);
    hown[((1 * 2 + 1) << 8) + (u << 4) + b] = __ldg(&h2i[sidx]);
    hown[((2 * 2 + 1) << 8) + (u << 4) + b] = __ldg(&h3i[sidx]);
    __syncthreads();
    cluster_sync();

    for (int t = 0; t < T_STEPS; t++) {
        const int pc = t & 1, pp = pc ^ 1;
        do_layer<0, 192>(smraw, hown_addr, x, out, t, pc, pp, tid, gid, bgb, bL0, c1r);
        do_layer<1, 256>(smraw, hown_addr, x, out, t, pc, pp, tid, gid, bgb, bL1, c2r);
        do_layer<2, 256>(smraw, hown_addr, x, out, t, pc, pp, tid, gid, bgb, bL2, c3r);
    }
}

extern "C" void kernel_launch(void* const* d_in, const int* in_sizes, int n_in,
                              void* d_out, int out_size) {
    (void)in_sizes; (void)n_in; (void)out_size;
    const float* x  = (const float*)d_in[0];
    const float* W1 = (const float*)d_in[1];
    const float* b1 = (const float*)d_in[2];
    const float* W2 = (const float*)d_in[3];
    const float* b2 = (const float*)d_in[4];
    const float* W3 = (const float*)d_in[5];
    const float* b3 = (const float*)d_in[6];
    const float* h1 = (const float*)d_in[7];
    const float* c1 = (const float*)d_in[8];
    const float* h2 = (const float*)d_in[9];
    const float* c2 = (const float*)d_in[10];
    const float* h3 = (const float*)d_in[11];
    const float* c3 = (const float*)d_in[12];
    float* out = (float*)d_out;

    cudaFuncSetAttribute(convlstm_kernel,
                         cudaFuncAttributeMaxDynamicSharedMemorySize, SMEM_TOTAL);
    convlstm_kernel<<<128, 256, SMEM_TOTAL>>>(x, W1, b1, W2, b2, W3, b3,
                                              h1, c1, h2, c2, h3, c3, out);
}

// round 5
// speedup vs baseline: 2.4344x; 2.4344x over previous
#include <cuda_runtime.h>
#include <cstdint>

// ============================================================================
// ConvLSTMEncoder == 3-layer LSTM (K=3 conv over length-1 dim -> center tap).
//   B=256, T=512, CIN=64, H=128.  gates[b,4H] = [in; h] @ Wc^T + bias
// Round-4: SKEWED LAYER PIPELINE. At macro-step s compute
//   L0(t=s), L1(t=s-1), L2(t=s-2)  -> ONE cross-CTA barrier per macro-step
//   (514 barriers instead of 1536). Shared input buffer
//   z = [x(s) | h0(s-1) | h1(s-2) | h2(s-3)]  (448 rows x 16 batch):
//   L0 reads rows 0..191, L1 rows 64..319, L2 rows 192..447.
// Layout: 128 CTAs = 16 batch-groups x 8 gate-slices (64 gate rows/CTA/layer),
//   weights fp32 in SMEM, h exchanged via L2 (__device__ buffer) + monotonic
//   counter barrier (round-1 proven machinery; clusters regressed in R3).
// GEMV: 256 thr, 8 warps = 2 row-groups x 4 k-quarters. Lane = 8 rows x 2
//   batches, row-pair u64 accumulators, fma.rn.f32x2; z plain in smem,
//   duplicated per-k via 1 mov.b64.
// ============================================================================

#define T_STEPS 512

// smem float offsets:
#define WOFF_L0 0
#define WOFF_L1 12288
#define WOFF_L2 28672
#define ZD_OFF  45056                 // z: [448][17] floats  (7616)
#define GB_OFF  52672                 // gbuf: [4][16][66] floats (4224)
#define SMEM_FLOATS 56896
#define SMEM_BYTES  (SMEM_FLOATS * 4) // 227584

__device__ float    g_hbuf[3 * 2 * 128 * 256];  // [layer][parity][unit][batch]
__device__ unsigned g_ctr[16];                  // per-group barrier counters

__global__ void reset_ctr_kernel() {
    if (threadIdx.x < 16) g_ctr[threadIdx.x] = 0u;
}

__device__ __forceinline__ float fast_rcp(float x) {
    float r; asm("rcp.approx.f32 %0, %1;" : "=f"(r) : "f"(x)); return r;
}
__device__ __forceinline__ float sigm(float x) {
    return fast_rcp(1.0f + __expf(-x));
}
__device__ __forceinline__ float tanh_f(float x) {
    x = fminf(fmaxf(x, -15.0f), 15.0f);
    float e = __expf(-2.0f * x);
    return (1.0f - e) * fast_rcp(1.0f + e);
}

#define FMA2(acc, a, b) asm("fma.rn.f32x2 %0, %1, %2, %0;" : "+l"(acc) : "l"(a), "l"(b))
#define DUP2(d, s)      asm("mov.b64 %0, {%1, %1};" : "=l"(d) : "r"(__float_as_uint(s)))

// All-thread fence + counter barrier among the 8 CTAs of one batch-group.
__device__ __forceinline__ void group_barrier(int grp, unsigned target) {
    __threadfence();
    __syncthreads();
    if (threadIdx.x == 0) {
        atomicAdd(&g_ctr[grp], 1u);
        unsigned v;
        for (;;) {
            asm volatile("ld.global.acquire.gpu.u32 %0, [%1];"
                         : "=r"(v) : "l"(&g_ctr[grp]) : "memory");
            if (v >= target) break;
            __nanosleep(32);
        }
    }
    __syncthreads();
}

// GEMV tile: KD/4 k-iters, 8 rows x 2 batches per lane, row-pair accumulators.
template<int KD>
__device__ __forceinline__ void gemv_store(
    const float* __restrict__ Wcol,   // Wsm + Loff + kq*(KD/4)*64 + rg*32 + oct*8
    const float* __restrict__ zcol,   // zd + (zoff + kq*(KD/4))*17 + 2*pr
    float* __restrict__ gdst)         // gbuf + kq*1056 + (2*pr)*66 + rg*32 + oct*8
{
    unsigned long long a0 = 0, a1 = 0, a2 = 0, a3 = 0;
    unsigned long long a4 = 0, a5 = 0, a6 = 0, a7 = 0;
#pragma unroll 8
    for (int k = 0; k < KD / 4; k++) {
        ulonglong2 wa = *(const ulonglong2*)(Wcol + k * 64);      // rows r0..r0+3
        ulonglong2 wb = *(const ulonglong2*)(Wcol + k * 64 + 4);  // rows r0+4..r0+7
        float z0 = zcol[k * 17];
        float z1 = zcol[k * 17 + 1];
        unsigned long long zz0, zz1;
        DUP2(zz0, z0); DUP2(zz1, z1);
        FMA2(a0, wa.x, zz0); FMA2(a1, wa.y, zz0);
        FMA2(a2, wb.x, zz0); FMA2(a3, wb.y, zz0);
        FMA2(a4, wa.x, zz1); FMA2(a5, wa.y, zz1);
        FMA2(a6, wb.x, zz1); FMA2(a7, wb.y, zz1);
    }
    *(unsigned long long*)(gdst + 0)      = a0;
    *(unsigned long long*)(gdst + 2)      = a1;
    *(unsigned long long*)(gdst + 4)      = a2;
    *(unsigned long long*)(gdst + 6)      = a3;
    *(unsigned long long*)(gdst + 66 + 0) = a4;
    *(unsigned long long*)(gdst + 66 + 2) = a5;
    *(unsigned long long*)(gdst + 66 + 4) = a6;
    *(unsigned long long*)(gdst + 66 + 6) = a7;
}

__global__ void __launch_bounds__(256, 1) convlstm_kernel(
    const float* __restrict__ x,
    const float* __restrict__ W1, const float* __restrict__ b1,
    const float* __restrict__ W2, const float* __restrict__ b2,
    const float* __restrict__ W3, const float* __restrict__ b3,
    const float* __restrict__ h1i, const float* __restrict__ c1i,
    const float* __restrict__ h2i, const float* __restrict__ c2i,
    const float* __restrict__ h3i, const float* __restrict__ c3i,
    float* __restrict__ out)
{
    extern __shared__ float sm[];
    float* Wsm  = sm;
    float* zd   = sm + ZD_OFF;
    float* gbuf = sm + GB_OFF;

    const int tid = threadIdx.x;
    const int gid = blockIdx.x & 7;    // gate-slice: hidden units [16*gid, 16*gid+16)
    const int bg  = blockIdx.x >> 3;   // batch group: batches [16*bg, 16*bg+16)
    const int bgb = bg << 4;

    // ---- Prologue: weight slices (center tap), [k][row64] per layer ----
    for (int idx = tid; idx < 192 * 64; idx += 256) {
        int k = idx >> 6, r = idx & 63;
        int grow = ((r >> 4) << 7) | (gid << 4) | (r & 15);  // gate*128 + gid*16 + u
        Wsm[WOFF_L0 + idx] = W1[(size_t)grow * 576 + k * 3 + 1];
    }
    for (int idx = tid; idx < 256 * 64; idx += 256) {
        int k = idx >> 6, r = idx & 63;
        int grow = ((r >> 4) << 7) | (gid << 4) | (r & 15);
        Wsm[WOFF_L1 + idx] = W2[(size_t)grow * 768 + k * 3 + 1];
        Wsm[WOFF_L2 + idx] = W3[(size_t)grow * 768 + k * 3 + 1];
    }

    // ---- per-thread (u,b) registers: bias + c state ----
    const int u = tid >> 4, b = tid & 15;
    const int gub = (gid << 4) | u;
    float4 bL0 = make_float4(__ldg(&b1[gub]), __ldg(&b1[128 + gub]),
                             __ldg(&b1[256 + gub]), __ldg(&b1[384 + gub]));
    float4 bL1 = make_float4(__ldg(&b2[gub]), __ldg(&b2[128 + gub]),
                             __ldg(&b2[256 + gub]), __ldg(&b2[384 + gub]));
    float4 bL2 = make_float4(__ldg(&b3[gub]), __ldg(&b3[128 + gub]),
                             __ldg(&b3[256 + gub]), __ldg(&b3[384 + gub]));
    const int sidx = (bgb + b) * 128 + gub;
    float c0r = __ldg(&c1i[sidx]);
    float c1r = __ldg(&c2i[sidx]);
    float c2r = __ldg(&c3i[sidx]);

    // ---- publish initial h into both parities ----
    {
        float h0 = __ldg(&h1i[sidx]), h1v = __ldg(&h2i[sidx]), h2v = __ldg(&h3i[sidx]);
        int hb = gub * 256 + bgb + b;
#pragma unroll
        for (int par = 0; par < 2; par++) {
            g_hbuf[(0 * 2 + par) * 32768 + hb] = h0;
            g_hbuf[(1 * 2 + par) * 32768 + hb] = h1v;
            g_hbuf[(2 * 2 + par) * 32768 + hb] = h2v;
        }
    }
    unsigned target = 8;
    group_barrier(bg, target); target += 8;

    // GEMV lane geometry
    const int warp = tid >> 5, lane = tid & 31;
    const int rg = warp & 1;             // row-group (32 rows)
    const int kq = warp >> 1;            // k-quarter
    const int oct = lane & 3;            // row-octet within group
    const int pr  = lane >> 2;           // batch-pair (0..7)
    const int wro = rg * 32 + oct * 8;   // row offset 0..56
    float* gdst = gbuf + kq * 1056 + (2 * pr) * 66 + wro;

    // ======================= macro-step pipeline =======================
    for (int s = 0; s < T_STEPS + 2; s++) {
        const int pc = s & 1, pp = pc ^ 1;

        // ---- assemble z = [x(s) | h0 | h1 | h2] (plain floats, stride 17) ----
        if (s < T_STEPS) {
            const float* xb = x + (size_t)bgb * (T_STEPS * 64) + (size_t)s * 64;
#pragma unroll
            for (int i = 0; i < 4; i++) {
                int idx = tid + (i << 8);
                int bb = idx >> 6, k = idx & 63;
                zd[k * 17 + bb] = __ldg(&xb[(size_t)bb * (T_STEPS * 64) + k]);
            }
        }
#pragma unroll
        for (int Lh = 0; Lh < 3; Lh++) {
            const float* src = &g_hbuf[(Lh * 2 + pp) * 32768 + bgb];
#pragma unroll
            for (int i = 0; i < 2; i++) {
                int idx = tid + (i << 8);
                int unit = idx >> 2, b4 = (idx & 3) << 2;
                float4 v = __ldcg((const float4*)&src[unit * 256 + b4]);
                float* d = &zd[(64 + (Lh << 7) + unit) * 17 + b4];
                d[0] = v.x; d[1] = v.y; d[2] = v.z; d[3] = v.w;
            }
        }
        __syncthreads();

        // -------- L0: t = s  (z rows 0..191) --------
        if (s < T_STEPS) {
            gemv_store<192>(Wsm + WOFF_L0 + kq * 48 * 64 + wro,
                            zd + (kq * 48) * 17 + 2 * pr, gdst);
            __syncthreads();
            float gi = bL0.x, gf = bL0.y, go = bL0.z, gg = bL0.w;
#pragma unroll
            for (int q = 0; q < 4; q++) {
                const float* gb = gbuf + q * 1056 + b * 66;
                gi += gb[u]; gf += gb[16 + u]; go += gb[32 + u]; gg += gb[48 + u];
            }
            float cn = sigm(gf) * c0r + sigm(gi) * tanh_f(gg);
            float hn = sigm(go) * tanh_f(cn);
            c0r = cn;
            g_hbuf[(0 * 2 + pc) * 32768 + gub * 256 + bgb + b] = hn;
        }
        __syncthreads();

        // -------- L1: t = s-1  (z rows 64..319) --------
        if (s >= 1 && s <= T_STEPS) {
            gemv_store<256>(Wsm + WOFF_L1 + kq * 64 * 64 + wro,
                            zd + (64 + kq * 64) * 17 + 2 * pr, gdst);
            __syncthreads();
            float gi = bL1.x, gf = bL1.y, go = bL1.z, gg = bL1.w;
#pragma unroll
            for (int q = 0; q < 4; q++) {
                const float* gb = gbuf + q * 1056 + b * 66;
                gi += gb[u]; gf += gb[16 + u]; go += gb[32 + u]; gg += gb[48 + u];
            }
            float cn = sigm(gf) * c1r + sigm(gi) * tanh_f(gg);
            float hn = sigm(go) * tanh_f(cn);
            c1r = cn;
            g_hbuf[(1 * 2 + pc) * 32768 + gub * 256 + bgb + b] = hn;
        }
        __syncthreads();

        // -------- L2: t = s-2  (z rows 192..447) --------
        if (s >= 2) {
            gemv_store<256>(Wsm + WOFF_L2 + kq * 64 * 64 + wro,
                            zd + (192 + kq * 64) * 17 + 2 * pr, gdst);
            __syncthreads();
            float gi = bL2.x, gf = bL2.y, go = bL2.z, gg = bL2.w;
#pragma unroll
            for (int q = 0; q < 4; q++) {
                const float* gb = gbuf + q * 1056 + b * 66;
                gi += gb[u]; gf += gb[16 + u]; go += gb[32 + u]; gg += gb[48 + u];
            }
            float cn = sigm(gf) * c2r + sigm(gi) * tanh_f(gg);
            float hn = sigm(go) * tanh_f(cn);
            c2r = cn;
            g_hbuf[(2 * 2 + pc) * 32768 + gub * 256 + bgb + b] = hn;
            if (s == T_STEPS + 1)
                out[(size_t)(bgb + b) * 128 + gub] = hn;
        }

        group_barrier(bg, target); target += 8;
    }
}

extern "C" void kernel_launch(void* const* d_in, const int* in_sizes, int n_in,
                              void* d_out, int out_size) {
    (void)in_sizes; (void)n_in; (void)out_size;
    const float* x  = (const float*)d_in[0];
    const float* W1 = (const float*)d_in[1];
    const float* b1 = (const float*)d_in[2];
    const float* W2 = (const float*)d_in[3];
    const float* b2 = (const float*)d_in[4];
    const float* W3 = (const float*)d_in[5];
    const float* b3 = (const float*)d_in[6];
    const float* h1 = (const float*)d_in[7];
    const float* c1 = (const float*)d_in[8];
    const float* h2 = (const float*)d_in[9];
    const float* c2 = (const float*)d_in[10];
    const float* h3 = (const float*)d_in[11];
    const float* c3 = (const float*)d_in[12];
    float* out = (float*)d_out;

    cudaFuncSetAttribute(convlstm_kernel,
                         cudaFuncAttributeMaxDynamicSharedMemorySize, SMEM_BYTES);
    reset_ctr_kernel<<<1, 32>>>();
    convlstm_kernel<<<128, 256, SMEM_BYTES>>>(x, W1, b1, W2, b2, W3, b3,
                                              h1, c1, h2, c2, h3, c3, out);
}